// round 9
// baseline (speedup 1.0000x reference)
#include <cuda_runtime.h>
#include <cuda_fp16.h>
#include <math.h>
#include <stdint.h>

// Problem constants
#define BB   4
#define CC   32
#define HH   64
#define WW   64
#define DD   288          // C*K*K
#define EE   144          // D/2
#define NHD  8            // heads
#define DHH  18           // head dim
#define SFN  4            // split factor
#define NTOK 4096         // H*W tokens per batch
#define NSEG 1024         // NTOK / SF
#define MTOT (BB*NTOK)    // 16384 tokens total

// weight buffer layout (f16), per layer
#define WR_ELEMS   (EE*DD)
#define WQKV_ELEMS (3*EE*EE)
#define WE_ELEMS   (DD*EE)
#define WL_STRIDE  (WR_ELEMS + WQKV_ELEMS + WE_ELEMS)
#define WQKV_OFF   WR_ELEMS
#define WE_OFF     (WR_ELEMS + WQKV_ELEMS)

// ---- f16 mma / ldmatrix helpers --------------------------------------------
__device__ __forceinline__ void mma_f16(float* c, const uint32_t* a, uint32_t b0, uint32_t b1) {
    asm("mma.sync.aligned.m16n8k16.row.col.f32.f16.f16.f32 "
        "{%0,%1,%2,%3},{%4,%5,%6,%7},{%8,%9},{%0,%1,%2,%3};"
        : "+f"(c[0]), "+f"(c[1]), "+f"(c[2]), "+f"(c[3])
        : "r"(a[0]), "r"(a[1]), "r"(a[2]), "r"(a[3]), "r"(b0), "r"(b1));
}
__device__ __forceinline__ void ldsm_x4(uint32_t* r, uint32_t addr) {
    asm volatile("ldmatrix.sync.aligned.m8n8.x4.shared.b16 {%0,%1,%2,%3},[%4];"
        : "=r"(r[0]), "=r"(r[1]), "=r"(r[2]), "=r"(r[3]) : "r"(addr));
}
__device__ __forceinline__ void ldsm_x2(uint32_t* r, uint32_t addr) {
    asm volatile("ldmatrix.sync.aligned.m8n8.x2.shared.b16 {%0,%1},[%2];"
        : "=r"(r[0]), "=r"(r[1]) : "r"(addr));
}
__device__ __forceinline__ void ldsm_x2t(uint32_t* r, uint32_t addr) {
    asm volatile("ldmatrix.sync.aligned.m8n8.x2.trans.shared.b16 {%0,%1},[%2];"
        : "=r"(r[0]), "=r"(r[1]) : "r"(addr));
}
__device__ __forceinline__ uint32_t cvth2(float lo, float hi) {
    uint32_t r; asm("cvt.rn.f16x2.f32 %0,%1,%2;" : "=r"(r) : "f"(hi), "f"(lo)); return r;
}
__device__ __forceinline__ uint32_t ex2h2(uint32_t x) {
    uint32_t r; asm("ex2.approx.f16x2 %0,%1;" : "=r"(r) : "r"(x)); return r;
}
__device__ __forceinline__ uint32_t packh2(float lo, float hi) {
    __half2 h = __floats2half2_rn(lo, hi);
    return *reinterpret_cast<uint32_t*>(&h);
}

// Scratch (device globals: allocation-free rule)
__device__ float  g_t[BB*CC*HH*WW];        // current image (fp32)
__device__ float  g_br[DD*MTOT];           // EMHA branch out, fp32 D-MAJOR [d][tok]
__device__ float  g_ps[MTOT], g_pq[MTOT];  // per-pixel channel sum / sumsq
__device__ float  g_mu[MTOT], g_rstd[MTOT];// per-token LN stats
__device__ __half g_xr_h[MTOT*EE];         // reduced tokens (f16)
__device__ __half g_qkv_h[MTOT*3*EE];      // qkv (f16, Q pre-scaled)
__device__ __half g_o_h[MTOT*EE];          // attention output (f16)
__device__ __half g_w_h[3*WL_STRIDE];      // converted weights, 3 layers
__device__ float  g_wgsum[3*EE], g_wbb[3*EE]; // LN-fold constants per layer

// ---------------------------------------------------------------------------
// Weight conversion fp32 -> f16. wr rows scaled by ln_g (LN fold);
// Q-rows of wqkv pre-scaled by 18^-0.5*log2(e).
// ---------------------------------------------------------------------------
__global__ void wconv_kernel(const float* __restrict__ wr,
                             const float* __restrict__ wqkv,
                             const float* __restrict__ we,
                             const float* __restrict__ lng,
                             __half* __restrict__ dst)
{
    const float qs = 0.235702260395515841f * 1.4426950408889634f;
    int i = blockIdx.x * 256 + threadIdx.x;
    if (i >= WL_STRIDE) return;
    float v;
    if (i < WR_ELEMS) v = wr[i] * lng[i % DD];
    else if (i < WE_OFF) {
        int j = i - WQKV_OFF;
        v = wqkv[j];
        if (j < EE * EE) v *= qs;
    } else v = we[i - WE_OFF];
    dst[i] = __float2half(v);
}

// wgsum[e] = sum_d wr[e,d]*g[d];  wbb[e] = sum_d wr[e,d]*b[d] + br[e]
__global__ void wsum_kernel(const float* __restrict__ wr,
                            const float* __restrict__ lng,
                            const float* __restrict__ lnb,
                            const float* __restrict__ br,
                            float* __restrict__ wgsum, float* __restrict__ wbb)
{
    int e = blockIdx.x, lane = threadIdx.x;
    float sg = 0.f, sb = 0.f;
    for (int d = lane; d < DD; d += 32) {
        float w = wr[e*DD + d];
        sg = fmaf(w, lng[d], sg);
        sb = fmaf(w, lnb[d], sb);
    }
    #pragma unroll
    for (int o = 16; o > 0; o >>= 1) {
        sg += __shfl_xor_sync(0xffffffffu, sg, o);
        sb += __shfl_xor_sync(0xffffffffu, sb, o);
    }
    if (lane == 0) { wgsum[e] = sg; wbb[e] = sb + br[e]; }
}

// ---------------------------------------------------------------------------
// LN stats, separable: per-pixel channel sums, then 3x3 box -> mu/rstd.
// ---------------------------------------------------------------------------
__global__ void stats_kernel(const float* __restrict__ img)
{
    int p = blockIdx.x * 256 + threadIdx.x;   // token == pixel index
    if (p >= MTOT) return;
    int b = p >> 12, hw = p & (NTOK - 1);
    const float* base = img + (size_t)b*CC*HH*WW + hw;
    float s = 0.f, q = 0.f;
    #pragma unroll
    for (int c = 0; c < CC; c++) {
        float v = base[c * HH * WW];
        s += v; q = fmaf(v, v, q);
    }
    g_ps[p] = s; g_pq[p] = q;
}

__global__ void lnstat_kernel()
{
    int p = blockIdx.x * 256 + threadIdx.x;
    if (p >= MTOT) return;
    int b = p >> 12, hw = p & (NTOK - 1);
    int h = hw >> 6, w = hw & 63;
    const float* ps = g_ps + b * NTOK;
    const float* pq = g_pq + b * NTOK;
    float s = 0.f, q = 0.f;
    #pragma unroll
    for (int i = 0; i < 3; i++) {
        int hh = h + i - 1;
        if ((unsigned)hh >= HH) continue;
        #pragma unroll
        for (int j = 0; j < 3; j++) {
            int ww = w + j - 1;
            if ((unsigned)ww >= WW) continue;
            s += ps[hh*WW + ww];
            q += pq[hh*WW + ww];
        }
    }
    float mu = s * (1.f / DD);
    g_mu[p] = mu;
    g_rstd[p] = rsqrtf(q * (1.f / DD) - mu*mu + 1e-5f);
}

// ---------------------------------------------------------------------------
// GEMM1: xr = LN(unfold(img)) @ (wr·g)^T folded — A gathered DIRECTLY from the
// image, LN applied in the epilogue:  v = rstd·(acc − mu·wgsum) + wbb.
// CTA tile 128x48, warp tile 32x24, k-chunk 48 (6 chunks over D=288).
// ---------------------------------------------------------------------------
#define APITCH 56
__global__ __launch_bounds__(256) void gemm1_kernel(
    const float* __restrict__ img,
    const __half* __restrict__ Wg,
    const float* __restrict__ wgsum,
    const float* __restrict__ wbb,
    __half* __restrict__ Cout)
{
    __shared__ __half As[128*APITCH];
    __shared__ __half Bs[48*APITCH];

    int tid = threadIdx.x;
    int warp = tid >> 5, lane = tid & 31;
    int g = lane >> 2, t = lane & 3;
    int wm = warp & 3, wn = warp >> 2;
    int rowB = blockIdx.y * 128;
    int colB = blockIdx.x * 48;
    int b  = rowB >> 12;
    int h0 = (rowB & (NTOK-1)) >> 6;
    const float* ibase = img + (size_t)b*CC*HH*WW;

    float acc[2][3][4];
    #pragma unroll
    for (int i = 0; i < 2; i++)
        #pragma unroll
        for (int j = 0; j < 3; j++)
            #pragma unroll
            for (int k = 0; k < 4; k++) acc[i][j][k] = 0.f;

    uint32_t asbase = (uint32_t)__cvta_generic_to_shared(As);
    uint32_t bsbase = (uint32_t)__cvta_generic_to_shared(Bs);
    int lr = lane & 7, lq = (lane >> 3) & 3;
    uint32_t aoff0 = asbase + (((wm*32 + lr + (lq&1)*8) * APITCH + (lq>>1)*8) << 1);
    uint32_t aoff1 = aoff0 + ((16*APITCH) << 1);
    uint32_t boff4 = bsbase + (((wn*24 + lr + (lq>>1)*8) * APITCH + (lq&1)*8) << 1);
    uint32_t boff2 = bsbase + (((wn*24 + 16 + lr) * APITCH + ((lane>>3)&1)*8) << 1);

    for (int kc = 0; kc < DD; kc += 48) {
        // stage A: gather 128 tokens x 48 d-cols straight from the image
        #pragma unroll
        for (int it = 0; it < 24; it++) {
            int idx = tid + it*256;           // < 6144
            int dcol = idx >> 7, tokrel = idx & 127;
            int d = kc + dcol;
            int c = d / 9, r = d - 9*c;
            int kh = r / 3, kw = r - 3*kh;
            int hh = h0 + (tokrel >> 6) + kh - 1;
            int ww = (tokrel & 63) + kw - 1;
            float v = 0.f;
            if ((unsigned)hh < HH && (unsigned)ww < WW)
                v = ibase[(c*HH + hh)*WW + ww];
            As[tokrel*APITCH + dcol] = __float2half(v);
        }
        // stage B (wg rows)
        {
            const uint4* wsrc = reinterpret_cast<const uint4*>(Wg);
            int idx = tid;
            if (idx < 288) {
                int row = idx / 6, seg = idx - row*6;
                uint4 v = wsrc[((size_t)(colB + row) * DD + kc + seg*8) >> 3];
                *reinterpret_cast<uint4*>(&Bs[row*APITCH + seg*8]) = v;
            }
            idx = tid + 256;
            if (idx < 288) {
                int row = idx / 6, seg = idx - row*6;
                uint4 v = wsrc[((size_t)(colB + row) * DD + kc + seg*8) >> 3];
                *reinterpret_cast<uint4*>(&Bs[row*APITCH + seg*8]) = v;
            }
        }
        __syncthreads();
        #pragma unroll
        for (int kk = 0; kk < 48; kk += 16) {
            uint32_t a0[4], a1[4], b01[4], b2[2];
            ldsm_x4(a0, aoff0 + (kk << 1));
            ldsm_x4(a1, aoff1 + (kk << 1));
            ldsm_x4(b01, boff4 + (kk << 1));
            ldsm_x2(b2, boff2 + (kk << 1));
            mma_f16(acc[0][0], a0, b01[0], b01[1]);
            mma_f16(acc[0][1], a0, b01[2], b01[3]);
            mma_f16(acc[0][2], a0, b2[0],  b2[1]);
            mma_f16(acc[1][0], a1, b01[0], b01[1]);
            mma_f16(acc[1][1], a1, b01[2], b01[3]);
            mma_f16(acc[1][2], a1, b2[0],  b2[1]);
        }
        __syncthreads();
    }

    uint32_t* C = reinterpret_cast<uint32_t*>(Cout);
    #pragma unroll
    for (int mt = 0; mt < 2; mt++) {
        int r0 = rowB + wm*32 + mt*16 + g;
        int r1 = r0 + 8;
        float mu0 = g_mu[r0], rs0 = g_rstd[r0];
        float mu1 = g_mu[r1], rs1 = g_rstd[r1];
        #pragma unroll
        for (int nt = 0; nt < 3; nt++) {
            int cc = colB + wn*24 + nt*8 + 2*t;
            float s0 = wgsum[cc], s1 = wgsum[cc+1];
            float w0 = wbb[cc],   w1 = wbb[cc+1];
            float v0 = rs0*(acc[mt][nt][0] - mu0*s0) + w0;
            float v1 = rs0*(acc[mt][nt][1] - mu0*s1) + w1;
            float v2 = rs1*(acc[mt][nt][2] - mu1*s0) + w0;
            float v3 = rs1*(acc[mt][nt][3] - mu1*s1) + w1;
            C[((size_t)r0 * EE + cc) >> 1] = packh2(v0, v1);
            C[((size_t)r1 * EE + cc) >> 1] = packh2(v2, v3);
        }
    }
}

// ---------------------------------------------------------------------------
// f16 GEMM (GEMM2/GEMM3), smem-staged + ldmatrix, as round 7.
// ---------------------------------------------------------------------------
template<int K, bool BOUT>
__global__ __launch_bounds__(256) void gemm_h_kernel(
    const __half* __restrict__ A, const __half* __restrict__ W,
    const float* __restrict__ bias,
    void* __restrict__ Cout, int Ncol)
{
    __shared__ __half As[128*APITCH];
    __shared__ __half Bs[48*APITCH];

    int tid = threadIdx.x;
    int warp = tid >> 5, lane = tid & 31;
    int g = lane >> 2, t = lane & 3;
    int wm = warp & 3, wn = warp >> 2;
    int rowB = blockIdx.y * 128;
    int colB = blockIdx.x * 48;

    float acc[2][3][4];
    #pragma unroll
    for (int i = 0; i < 2; i++)
        #pragma unroll
        for (int j = 0; j < 3; j++)
            #pragma unroll
            for (int k = 0; k < 4; k++) acc[i][j][k] = 0.f;

    uint32_t asbase = (uint32_t)__cvta_generic_to_shared(As);
    uint32_t bsbase = (uint32_t)__cvta_generic_to_shared(Bs);
    int lr = lane & 7, lq = (lane >> 3) & 3;
    uint32_t aoff0 = asbase + (((wm*32 + lr + (lq&1)*8) * APITCH + (lq>>1)*8) << 1);
    uint32_t aoff1 = aoff0 + ((16*APITCH) << 1);
    uint32_t boff4 = bsbase + (((wn*24 + lr + (lq>>1)*8) * APITCH + (lq&1)*8) << 1);
    uint32_t boff2 = bsbase + (((wn*24 + 16 + lr) * APITCH + ((lane>>3)&1)*8) << 1);

    for (int kc = 0; kc < K; kc += 48) {
        {
            const uint4* src = reinterpret_cast<const uint4*>(A);
            #pragma unroll
            for (int it = 0; it < 3; it++) {
                int idx = tid + it*256;
                int row = idx / 6, seg = idx - row*6;
                uint4 v = src[((size_t)(rowB + row) * K + kc + seg*8) >> 3];
                *reinterpret_cast<uint4*>(&As[row*APITCH + seg*8]) = v;
            }
            const uint4* wsrc = reinterpret_cast<const uint4*>(W);
            int idx = tid;
            if (idx < 288) {
                int row = idx / 6, seg = idx - row*6;
                uint4 v = wsrc[((size_t)(colB + row) * K + kc + seg*8) >> 3];
                *reinterpret_cast<uint4*>(&Bs[row*APITCH + seg*8]) = v;
            }
            idx = tid + 256;
            if (idx < 288) {
                int row = idx / 6, seg = idx - row*6;
                uint4 v = wsrc[((size_t)(colB + row) * K + kc + seg*8) >> 3];
                *reinterpret_cast<uint4*>(&Bs[row*APITCH + seg*8]) = v;
            }
        }
        __syncthreads();
        #pragma unroll
        for (int kk = 0; kk < 48; kk += 16) {
            uint32_t a0[4], a1[4], b01[4], b2[2];
            ldsm_x4(a0, aoff0 + (kk << 1));
            ldsm_x4(a1, aoff1 + (kk << 1));
            ldsm_x4(b01, boff4 + (kk << 1));
            ldsm_x2(b2, boff2 + (kk << 1));
            mma_f16(acc[0][0], a0, b01[0], b01[1]);
            mma_f16(acc[0][1], a0, b01[2], b01[3]);
            mma_f16(acc[0][2], a0, b2[0],  b2[1]);
            mma_f16(acc[1][0], a1, b01[0], b01[1]);
            mma_f16(acc[1][1], a1, b01[2], b01[3]);
            mma_f16(acc[1][2], a1, b2[0],  b2[1]);
        }
        __syncthreads();
    }

    #pragma unroll
    for (int mt = 0; mt < 2; mt++) {
        int r0 = rowB + wm*32 + mt*16 + g;
        int r1 = r0 + 8;
        #pragma unroll
        for (int nt = 0; nt < 3; nt++) {
            int cc = colB + wn*24 + nt*8 + 2*t;
            float v0 = acc[mt][nt][0], v1 = acc[mt][nt][1];
            float v2 = acc[mt][nt][2], v3 = acc[mt][nt][3];
            if (bias) {
                float b0 = bias[cc], b1 = bias[cc+1];
                v0 += b0; v1 += b1; v2 += b0; v3 += b1;
            }
            if (BOUT) {
                uint32_t* C = (uint32_t*)Cout;
                C[((size_t)r0 * Ncol + cc) >> 1] = packh2(v0, v1);
                C[((size_t)r1 * Ncol + cc) >> 1] = packh2(v2, v3);
            } else {
                float* C = (float*)Cout;
                size_t i00 = (size_t)cc*MTOT + r0, i10 = i00 + MTOT;
                size_t i01 = (size_t)cc*MTOT + r1, i11 = i01 + MTOT;
                C[i00] = v0; C[i10] = v1; C[i01] = v2; C[i11] = v3;
            }
        }
    }
}

// ---------------------------------------------------------------------------
// Attention: f16 flash, ex2.approx.f16x2, l via ones-column in V (d=18).
// v7: 2 q-tiles per warp in the j-loop — K/V ldmatrix shared across both.
// ---------------------------------------------------------------------------
#define KPITCH 40
#define VPITCH 24
#define ATTN_SMEM_BYTES ((NSEG*KPITCH + NSEG*VPITCH) * 2)   // 131072

__global__ __launch_bounds__(512) void attn_kernel()
{
    int seg  = blockIdx.x;
    int b    = seg / (NHD * SFN);
    int rest = seg % (NHD * SFN);
    int hd   = rest / SFN;
    int sp   = rest % SFN;
    int base = b * NTOK + sp * NSEG;
    const int QKVROW = 3 * EE;

    extern __shared__ __half smh[];
    __half* Ks = smh;                       // [NSEG][KPITCH]
    __half* Vs = smh + NSEG * KPITCH;       // [NSEG][VPITCH]

    const uint32_t* qk32 = reinterpret_cast<const uint32_t*>(g_qkv_h);
    uint32_t* Ks32 = reinterpret_cast<uint32_t*>(Ks);
    uint32_t* Vs32 = reinterpret_cast<uint32_t*>(Vs);

    for (int idx = threadIdx.x; idx < NSEG * (KPITCH/2); idx += 512) {
        int i = idx / (KPITCH/2), d2 = idx - i * (KPITCH/2);
        uint32_t v = 0u;
        if (d2 < 9)
            v = qk32[(((size_t)(base + i) * QKVROW + EE + hd * DHH) >> 1) + d2];
        Ks32[i * (KPITCH/2) + d2] = v;
    }
    for (int idx = threadIdx.x; idx < NSEG * (VPITCH/2); idx += 512) {
        int i = idx / (VPITCH/2), d2 = idx - i * (VPITCH/2);
        uint32_t v = 0u;
        if (d2 < 9)
            v = qk32[(((size_t)(base + i) * QKVROW + 2*EE + hd * DHH) >> 1) + d2];
        else if (d2 == 9)
            v = 0x00003C00u;                 // {1.0h, 0} -> l-ones at d=18
        Vs32[i * (VPITCH/2) + d2] = v;
    }
    __syncthreads();

    int lane = threadIdx.x & 31, warp = threadIdx.x >> 5;
    int g = lane >> 2, t = lane & 3;
    int lr = lane & 7, lq = (lane >> 3) & 3;

    uint32_t ksb = (uint32_t)__cvta_generic_to_shared(Ks);
    uint32_t vsb = (uint32_t)__cvta_generic_to_shared(Vs);
    uint32_t kaddr_base = ksb + (((lr + (lq>>1)*8) * KPITCH + (lq&1)*8) << 1);
    uint32_t vaddr_base = vsb + (((lane & 15) * VPITCH) << 1);

    uint32_t* o32 = reinterpret_cast<uint32_t*>(g_o_h);

    #pragma unroll
    for (int qp = 0; qp < 2; qp++) {
        int q0A = (warp + qp*32) * 16;     // qtiles: warp+qp*32 and +16
        int q0B = q0A + 256;

        const uint32_t* qAa = qk32 + (((size_t)(base + q0A + g)     * QKVROW + hd * DHH) >> 1);
        const uint32_t* qAb = qk32 + (((size_t)(base + q0A + g + 8) * QKVROW + hd * DHH) >> 1);
        const uint32_t* qBa = qk32 + (((size_t)(base + q0B + g)     * QKVROW + hd * DHH) >> 1);
        const uint32_t* qBb = qk32 + (((size_t)(base + q0B + g + 8) * QKVROW + hd * DHH) >> 1);

        uint32_t qa[2][4], qb[2][4];
        qa[0][0] = qAa[t];   qa[0][1] = qAb[t];
        qa[0][2] = qAa[t+4]; qa[0][3] = qAb[t+4];
        qa[1][0] = (t == 0) ? qAa[8] : 0u;
        qa[1][1] = (t == 0) ? qAb[8] : 0u;
        qa[1][2] = 0u; qa[1][3] = 0u;
        qb[0][0] = qBa[t];   qb[0][1] = qBb[t];
        qb[0][2] = qBa[t+4]; qb[0][3] = qBb[t+4];
        qb[1][0] = (t == 0) ? qBa[8] : 0u;
        qb[1][1] = (t == 0) ? qBb[8] : 0u;
        qb[1][2] = 0u; qb[1][3] = 0u;

        float oA[3][4], oB[3][4];
        #pragma unroll
        for (int dn = 0; dn < 3; dn++)
            #pragma unroll
            for (int i = 0; i < 4; i++) { oA[dn][i] = 0.f; oB[dn][i] = 0.f; }

        uint32_t kaddr = kaddr_base;
        uint32_t vaddr = vaddr_base;
        for (int j0 = 0; j0 < NSEG; j0 += 16) {
            uint32_t kf0[4], kf1[4];
            ldsm_x4(kf0, kaddr);
            ldsm_x4(kf1, kaddr + 32);

            float sA0[4] = {0.f,0.f,0.f,0.f}, sA1[4] = {0.f,0.f,0.f,0.f};
            float sB0[4] = {0.f,0.f,0.f,0.f}, sB1[4] = {0.f,0.f,0.f,0.f};
            mma_f16(sA0, qa[0], kf0[0], kf0[1]);
            mma_f16(sA1, qa[0], kf0[2], kf0[3]);
            mma_f16(sA0, qa[1], kf1[0], kf1[1]);
            mma_f16(sA1, qa[1], kf1[2], kf1[3]);
            mma_f16(sB0, qb[0], kf0[0], kf0[1]);
            mma_f16(sB1, qb[0], kf0[2], kf0[3]);
            mma_f16(sB0, qb[1], kf1[0], kf1[1]);
            mma_f16(sB1, qb[1], kf1[2], kf1[3]);

            uint32_t paA[4], paB[4];
            paA[0] = ex2h2(cvth2(sA0[0], sA0[1]));
            paA[1] = ex2h2(cvth2(sA0[2], sA0[3]));
            paA[2] = ex2h2(cvth2(sA1[0], sA1[1]));
            paA[3] = ex2h2(cvth2(sA1[2], sA1[3]));
            paB[0] = ex2h2(cvth2(sB0[0], sB0[1]));
            paB[1] = ex2h2(cvth2(sB0[2], sB0[3]));
            paB[2] = ex2h2(cvth2(sB1[0], sB1[1]));
            paB[3] = ex2h2(cvth2(sB1[2], sB1[3]));

            uint32_t vf[2];
            ldsm_x2t(vf, vaddr);
            mma_f16(oA[0], paA, vf[0], vf[1]);
            mma_f16(oB[0], paB, vf[0], vf[1]);
            ldsm_x2t(vf, vaddr + 16);
            mma_f16(oA[1], paA, vf[0], vf[1]);
            mma_f16(oB[1], paB, vf[0], vf[1]);
            ldsm_x2t(vf, vaddr + 32);
            mma_f16(oA[2], paA, vf[0], vf[1]);
            mma_f16(oB[2], paB, vf[0], vf[1]);

            kaddr += 16 * KPITCH * 2;
            vaddr += 16 * VPITCH * 2;
        }

        int srcl = (lane & 28) | 1;
        float lgA  = __shfl_sync(0xffffffffu, oA[2][0], srcl);
        float lgA8 = __shfl_sync(0xffffffffu, oA[2][2], srcl);
        float lgB  = __shfl_sync(0xffffffffu, oB[2][0], srcl);
        float lgB8 = __shfl_sync(0xffffffffu, oB[2][2], srcl);
        float igA = 1.f / lgA, igA8 = 1.f / lgA8;
        float igB = 1.f / lgB, igB8 = 1.f / lgB8;

        #pragma unroll
        for (int dn = 0; dn < 3; dn++) {
            int dc = dn * 8 + 2 * t;
            if (dc < DHH) {
                o32[((size_t)(base + q0A + g)     * EE + hd*DHH + dc) >> 1] = packh2(oA[dn][0]*igA,  oA[dn][1]*igA);
                o32[((size_t)(base + q0A + g + 8) * EE + hd*DHH + dc) >> 1] = packh2(oA[dn][2]*igA8, oA[dn][3]*igA8);
                o32[((size_t)(base + q0B + g)     * EE + hd*DHH + dc) >> 1] = packh2(oB[dn][0]*igB,  oB[dn][1]*igB);
                o32[((size_t)(base + q0B + g + 8) * EE + hd*DHH + dc) >> 1] = packh2(oB[dn][2]*igB8, oB[dn][3]*igB8);
            }
        }
    }
}

// ---------------------------------------------------------------------------
// Fold: t_next = m(h)·m(w)·t + gather(branch).  (fold∘unfold = diag(m))
// ---------------------------------------------------------------------------
__global__ void fold_kernel(const float* __restrict__ img)
{
    int idx = blockIdx.x * blockDim.x + threadIdx.x;
    if (idx >= BB*CC*HH*WW) return;
    int w = idx & 63;
    int h = (idx >> 6) & 63;
    int c = (idx >> 12) & 31;
    int b =  idx >> 17;

    float mh = (h == 0 || h == HH-1) ? 2.f : 3.f;
    float mw = (w == 0 || w == WW-1) ? 2.f : 3.f;
    float sum = img[idx] * (mh * mw);

    #pragma unroll
    for (int i = 0; i < 3; i++) {
        int hh = h + 1 - i;
        if (hh < 0 || hh >= HH) continue;
        #pragma unroll
        for (int j = 0; j < 3; j++) {
            int ww = w + 1 - j;
            if (ww < 0 || ww >= WW) continue;
            sum += g_br[(size_t)(c*9 + i*3 + j)*MTOT + b*NTOK + hh*WW + ww];
        }
    }
    g_t[idx] = sum;
}

// ---------------------------------------------------------------------------
// Final: out = x + elu(conv3x3(t) + conv_b)
// ---------------------------------------------------------------------------
__global__ void conv_elu_kernel(const float* __restrict__ x,
                                const float* __restrict__ cw,
                                const float* __restrict__ cb,
                                float* __restrict__ out)
{
    int idx = blockIdx.x * blockDim.x + threadIdx.x;
    if (idx >= BB*CC*HH*WW) return;
    int w  = idx & 63;
    int h  = (idx >> 6) & 63;
    int co = (idx >> 12) & 31;
    int b  =  idx >> 17;

    float sum = cb[co];
    for (int ci = 0; ci < CC; ci++) {
        const float* tplane = &g_t[((size_t)(b*CC + ci))*HH*WW];
        const float* wk = &cw[((size_t)(co*CC + ci))*9];
        #pragma unroll
        for (int kh = 0; kh < 3; kh++) {
            int hh = h + kh - 1;
            if (hh < 0 || hh >= HH) continue;
            #pragma unroll
            for (int kw = 0; kw < 3; kw++) {
                int ww = w + kw - 1;
                if (ww < 0 || ww >= WW) continue;
                sum = fmaf(tplane[hh*WW + ww], wk[kh*3 + kw], sum);
            }
        }
    }
    float e = sum > 0.f ? sum : expm1f(sum);
    out[idx] = x[idx] + e;
}

// ---------------------------------------------------------------------------
// Launch
// ---------------------------------------------------------------------------
extern "C" void kernel_launch(void* const* d_in, const int* in_sizes, int n_in,
                              void* d_out, int out_size)
{
    (void)in_sizes; (void)n_in; (void)out_size;
    const float* x     = (const float*)d_in[0];
    const float* ln_g  = (const float*)d_in[1];
    const float* ln_b  = (const float*)d_in[2];
    const float* convw = (const float*)d_in[3];
    const float* convb = (const float*)d_in[4];
    float* out = (float*)d_out;

    float *p_t, *p_br, *p_wgsum, *p_wbb;
    __half *p_xr, *p_qkv, *p_o, *p_w;
    cudaGetSymbolAddress((void**)&p_t,     g_t);
    cudaGetSymbolAddress((void**)&p_br,    g_br);
    cudaGetSymbolAddress((void**)&p_xr,    g_xr_h);
    cudaGetSymbolAddress((void**)&p_qkv,   g_qkv_h);
    cudaGetSymbolAddress((void**)&p_o,     g_o_h);
    cudaGetSymbolAddress((void**)&p_w,     g_w_h);
    cudaGetSymbolAddress((void**)&p_wgsum, g_wgsum);
    cudaGetSymbolAddress((void**)&p_wbb,   g_wbb);

    cudaFuncSetAttribute(attn_kernel, cudaFuncAttributeMaxDynamicSharedMemorySize, ATTN_SMEM_BYTES);

    const int NPIX = BB*CC*HH*WW;

    for (int L = 0; L < 3; L++) {
        const float* wr = (const float*)d_in[5 + 5*L + 0];
        const float* br = (const float*)d_in[5 + 5*L + 1];
        wconv_kernel<<<(WL_STRIDE + 255)/256, 256>>>(
            wr,
            (const float*)d_in[5 + 5*L + 2],
            (const float*)d_in[5 + 5*L + 3],
            ln_g,
            p_w + (size_t)L * WL_STRIDE);
        wsum_kernel<<<EE, 32>>>(wr, ln_g, ln_b, br,
                                p_wgsum + L*EE, p_wbb + L*EE);
    }

    for (int L = 0; L < 3; L++) {
        const float* be = (const float*)d_in[5 + 5*L + 4];
        const __half* wg   = p_w + (size_t)L * WL_STRIDE;
        const __half* wqkv = wg + WQKV_OFF;
        const __half* we   = wg + WE_OFF;
        const float* img = (L == 0) ? x : p_t;

        stats_kernel<<<MTOT/256, 256>>>(img);
        lnstat_kernel<<<MTOT/256, 256>>>();
        // xr = LN-folded (unfold(img) @ wg^T)  — direct image gather
        gemm1_kernel<<<dim3(EE/48, MTOT/128), 256>>>(
            img, wg, p_wgsum + L*EE, p_wbb + L*EE, p_xr);
        // qkv = xr @ wqkv^T        (f16 out, Q pre-scaled)
        gemm_h_kernel<144, true><<<dim3(3*EE/48, MTOT/128), 256>>>(
            p_xr, wqkv, nullptr, p_qkv, 3*EE);
        attn_kernel<<<BB*NHD*SFN, 512, ATTN_SMEM_BYTES>>>();
        // branch = o @ we^T + be   (fp32 d-major out)
        gemm_h_kernel<144, false><<<dim3(DD/48, MTOT/128), 256>>>(
            p_o, we, be, p_br, DD);
        // t = m·t + fold(branch)
        fold_kernel<<<(NPIX + 255)/256, 256>>>(img);
    }
    conv_elu_kernel<<<(NPIX + 255)/256, 256>>>(x, convw, convb, out);
}

// round 10
// speedup vs baseline: 1.0793x; 1.0793x over previous
#include <cuda_runtime.h>
#include <cuda_fp16.h>
#include <math.h>
#include <stdint.h>

// Problem constants
#define BB   4
#define CC   32
#define HH   64
#define WW   64
#define DD   288          // C*K*K
#define EE   144          // D/2
#define NHD  8            // heads
#define DHH  18           // head dim
#define SFN  4            // split factor
#define NTOK 4096         // H*W tokens per batch
#define NSEG 1024         // NTOK / SF
#define MTOT (BB*NTOK)    // 16384 tokens total

// weight buffer layout (f16), per layer
#define WR_ELEMS   (EE*DD)
#define WQKV_ELEMS (3*EE*EE)
#define WE_ELEMS   (DD*EE)
#define WL_STRIDE  (WR_ELEMS + WQKV_ELEMS + WE_ELEMS)
#define WQKV_OFF   WR_ELEMS
#define WE_OFF     (WR_ELEMS + WQKV_ELEMS)

// ---- f16 mma / ldmatrix helpers --------------------------------------------
__device__ __forceinline__ void mma_f16(float* c, const uint32_t* a, uint32_t b0, uint32_t b1) {
    asm("mma.sync.aligned.m16n8k16.row.col.f32.f16.f16.f32 "
        "{%0,%1,%2,%3},{%4,%5,%6,%7},{%8,%9},{%0,%1,%2,%3};"
        : "+f"(c[0]), "+f"(c[1]), "+f"(c[2]), "+f"(c[3])
        : "r"(a[0]), "r"(a[1]), "r"(a[2]), "r"(a[3]), "r"(b0), "r"(b1));
}
__device__ __forceinline__ void ldsm_x4(uint32_t* r, uint32_t addr) {
    asm volatile("ldmatrix.sync.aligned.m8n8.x4.shared.b16 {%0,%1,%2,%3},[%4];"
        : "=r"(r[0]), "=r"(r[1]), "=r"(r[2]), "=r"(r[3]) : "r"(addr));
}
__device__ __forceinline__ void ldsm_x2(uint32_t* r, uint32_t addr) {
    asm volatile("ldmatrix.sync.aligned.m8n8.x2.shared.b16 {%0,%1},[%2];"
        : "=r"(r[0]), "=r"(r[1]) : "r"(addr));
}
__device__ __forceinline__ void ldsm_x2t(uint32_t* r, uint32_t addr) {
    asm volatile("ldmatrix.sync.aligned.m8n8.x2.trans.shared.b16 {%0,%1},[%2];"
        : "=r"(r[0]), "=r"(r[1]) : "r"(addr));
}
__device__ __forceinline__ uint32_t cvth2(float lo, float hi) {
    uint32_t r; asm("cvt.rn.f16x2.f32 %0,%1,%2;" : "=r"(r) : "f"(hi), "f"(lo)); return r;
}
__device__ __forceinline__ uint32_t ex2h2(uint32_t x) {
    uint32_t r; asm("ex2.approx.f16x2 %0,%1;" : "=r"(r) : "r"(x)); return r;
}
__device__ __forceinline__ uint32_t packh2(float lo, float hi) {
    __half2 h = __floats2half2_rn(lo, hi);
    return *reinterpret_cast<uint32_t*>(&h);
}

// Scratch (device globals: allocation-free rule)
__device__ float  g_t[BB*CC*HH*WW];        // current image (fp32)
__device__ float  g_br[DD*MTOT];           // EMHA branch out, fp32 D-MAJOR [d][tok]
__device__ __half g_colsn_h[MTOT*DD];      // layernormed cols (f16, tok-major)
__device__ __half g_xr_h[MTOT*EE];         // reduced tokens (f16)
__device__ __half g_qkv_h[MTOT*3*EE];      // qkv (f16, Q pre-scaled)
__device__ __half g_o_h[MTOT*EE];          // attention output (f16)
__device__ __half g_w_h[3*WL_STRIDE];      // converted weights, 3 layers
__device__ int    g_offt[DD];              // packed unfold offsets

// ---------------------------------------------------------------------------
// One-time: packed unfold offsets. pk = (c*4096+(kh-1)*64+(kw-1)+65)
//                                      | kh<<20 | kw<<22
// ---------------------------------------------------------------------------
__global__ void offt_kernel()
{
    int d = threadIdx.x;
    if (d >= DD) return;
    int c = d / 9, r = d - 9*c;
    int kh = r / 3, kw = r - 3*kh;
    int off = c*4096 + (kh-1)*64 + (kw-1);
    g_offt[d] = (off + 65) | (kh << 20) | (kw << 22);
}

// ---------------------------------------------------------------------------
// Weight conversion fp32 -> f16, all 3 layers in ONE launch.
// Q-rows of wqkv pre-scaled by 18^-0.5*log2(e).
// ---------------------------------------------------------------------------
struct WPtrs {
    const float* wr[3];
    const float* wqkv[3];
    const float* we[3];
};
__global__ void wconv_kernel(WPtrs p, __half* __restrict__ dst)
{
    const float qs = 0.235702260395515841f * 1.4426950408889634f;
    int i = blockIdx.x * 256 + threadIdx.x;
    if (i >= 3 * WL_STRIDE) return;
    int L = i / WL_STRIDE;
    int j = i - L * WL_STRIDE;
    float v;
    if (j < WR_ELEMS) v = p.wr[L][j];
    else if (j < WE_OFF) {
        int k = j - WQKV_OFF;
        v = p.wqkv[L][k];
        if (k < EE * EE) v *= qs;
    } else v = p.we[L][j - WE_OFF];
    dst[i] = __float2half(v);
}

// ---------------------------------------------------------------------------
// Fused unfold + LayerNorm. One WARP per token; table-driven offsets (no
// div/mod, no bounds checks on the 94% interior fast path).
// ---------------------------------------------------------------------------
__global__ __launch_bounds__(256) void unfold_ln_kernel(
    const float* __restrict__ img,
    const float* __restrict__ lng,
    const float* __restrict__ lnb)
{
    __shared__ int soff[DD];
    for (int i = threadIdx.x; i < DD; i += 256) soff[i] = g_offt[i];
    __syncthreads();

    int warp = threadIdx.x >> 5, lane = threadIdx.x & 31;
    int tok = blockIdx.x * 8 + warp;
    int b = tok >> 12;
    int n = tok & (NTOK - 1);
    int h = n >> 6, w = n & 63;
    int base = b*CC*4096 + h*64 + w;

    float v[9];
    float s = 0.f, q = 0.f;
    if (h >= 1 && h <= 62 && w >= 1 && w <= 62) {
        #pragma unroll
        for (int i = 0; i < 9; i++) {
            int pk = soff[i*32 + lane];
            float x = img[base + (pk & 0xFFFFF) - 65];
            v[i] = x; s += x; q = fmaf(x, x, q);
        }
    } else {
        #pragma unroll
        for (int i = 0; i < 9; i++) {
            int pk = soff[i*32 + lane];
            int kh = (pk >> 20) & 3, kw = (pk >> 22) & 3;
            int hh = h + kh - 1, ww = w + kw - 1;
            float x = 0.f;
            if ((unsigned)hh < HH && (unsigned)ww < WW)
                x = img[base + (pk & 0xFFFFF) - 65];
            v[i] = x; s += x; q = fmaf(x, x, q);
        }
    }
    #pragma unroll
    for (int o = 16; o > 0; o >>= 1) {
        s += __shfl_xor_sync(0xffffffffu, s, o);
        q += __shfl_xor_sync(0xffffffffu, q, o);
    }
    float mu = s * (1.f / DD);
    float rstd = rsqrtf(q * (1.f / DD) - mu * mu + 1e-5f);
    #pragma unroll
    for (int i = 0; i < 9; i++) {
        int d = i * 32 + lane;
        g_colsn_h[(size_t)tok*DD + d] =
            __float2half((v[i] - mu) * rstd * __ldg(&lng[d]) + __ldg(&lnb[d]));
    }
}

// ---------------------------------------------------------------------------
// f16 GEMM, smem-staged + ldmatrix: C(M,N) = A(M,K)*W(N,K)^T (+bias)
// CTA 256 thr = 8 warps (4M x 2N); CTA tile 128x48; warp tile 32x24; k-chunk 48.
// BOUT=true: f16 packed tok-major out. BOUT=false: fp32 D-MAJOR out.
// ---------------------------------------------------------------------------
#define APITCH 56
template<int K, bool BOUT>
__global__ __launch_bounds__(256) void gemm_h_kernel(
    const __half* __restrict__ A, const __half* __restrict__ W,
    const float* __restrict__ bias,
    void* __restrict__ Cout, int Ncol)
{
    __shared__ __half As[128*APITCH];
    __shared__ __half Bs[48*APITCH];

    int tid = threadIdx.x;
    int warp = tid >> 5, lane = tid & 31;
    int g = lane >> 2, t = lane & 3;
    int wm = warp & 3, wn = warp >> 2;
    int rowB = blockIdx.y * 128;
    int colB = blockIdx.x * 48;

    float acc[2][3][4];
    #pragma unroll
    for (int i = 0; i < 2; i++)
        #pragma unroll
        for (int j = 0; j < 3; j++)
            #pragma unroll
            for (int k = 0; k < 4; k++) acc[i][j][k] = 0.f;

    uint32_t asbase = (uint32_t)__cvta_generic_to_shared(As);
    uint32_t bsbase = (uint32_t)__cvta_generic_to_shared(Bs);
    int lr = lane & 7, lq = (lane >> 3) & 3;
    uint32_t aoff0 = asbase + (((wm*32 + lr + (lq&1)*8) * APITCH + (lq>>1)*8) << 1);
    uint32_t aoff1 = aoff0 + ((16*APITCH) << 1);
    uint32_t boff4 = bsbase + (((wn*24 + lr + (lq>>1)*8) * APITCH + (lq&1)*8) << 1);
    uint32_t boff2 = bsbase + (((wn*24 + 16 + lr) * APITCH + ((lane>>3)&1)*8) << 1);

    for (int kc = 0; kc < K; kc += 48) {
        {
            const uint4* src = reinterpret_cast<const uint4*>(A);
            #pragma unroll
            for (int it = 0; it < 3; it++) {
                int idx = tid + it*256;
                int row = idx / 6, seg = idx - row*6;
                uint4 v = src[((size_t)(rowB + row) * K + kc + seg*8) >> 3];
                *reinterpret_cast<uint4*>(&As[row*APITCH + seg*8]) = v;
            }
            const uint4* wsrc = reinterpret_cast<const uint4*>(W);
            int idx = tid;
            if (idx < 288) {
                int row = idx / 6, seg = idx - row*6;
                uint4 v = wsrc[((size_t)(colB + row) * K + kc + seg*8) >> 3];
                *reinterpret_cast<uint4*>(&Bs[row*APITCH + seg*8]) = v;
            }
            idx = tid + 256;
            if (idx < 288) {
                int row = idx / 6, seg = idx - row*6;
                uint4 v = wsrc[((size_t)(colB + row) * K + kc + seg*8) >> 3];
                *reinterpret_cast<uint4*>(&Bs[row*APITCH + seg*8]) = v;
            }
        }
        __syncthreads();
        #pragma unroll
        for (int kk = 0; kk < 48; kk += 16) {
            uint32_t a0[4], a1[4], b01[4], b2[2];
            ldsm_x4(a0, aoff0 + (kk << 1));
            ldsm_x4(a1, aoff1 + (kk << 1));
            ldsm_x4(b01, boff4 + (kk << 1));
            ldsm_x2(b2, boff2 + (kk << 1));
            mma_f16(acc[0][0], a0, b01[0], b01[1]);
            mma_f16(acc[0][1], a0, b01[2], b01[3]);
            mma_f16(acc[0][2], a0, b2[0],  b2[1]);
            mma_f16(acc[1][0], a1, b01[0], b01[1]);
            mma_f16(acc[1][1], a1, b01[2], b01[3]);
            mma_f16(acc[1][2], a1, b2[0],  b2[1]);
        }
        __syncthreads();
    }

    #pragma unroll
    for (int mt = 0; mt < 2; mt++) {
        int r0 = rowB + wm*32 + mt*16 + g;
        int r1 = r0 + 8;
        #pragma unroll
        for (int nt = 0; nt < 3; nt++) {
            int cc = colB + wn*24 + nt*8 + 2*t;
            float v0 = acc[mt][nt][0], v1 = acc[mt][nt][1];
            float v2 = acc[mt][nt][2], v3 = acc[mt][nt][3];
            if (bias) {
                float b0 = bias[cc], b1 = bias[cc+1];
                v0 += b0; v1 += b1; v2 += b0; v3 += b1;
            }
            if (BOUT) {
                uint32_t* C = (uint32_t*)Cout;
                C[((size_t)r0 * Ncol + cc) >> 1] = packh2(v0, v1);
                C[((size_t)r1 * Ncol + cc) >> 1] = packh2(v2, v3);
            } else {
                float* C = (float*)Cout;
                size_t i00 = (size_t)cc*MTOT + r0, i10 = i00 + MTOT;
                size_t i01 = (size_t)cc*MTOT + r1, i11 = i01 + MTOT;
                C[i00] = v0; C[i10] = v1; C[i01] = v2; C[i11] = v3;
            }
        }
    }
}

// ---------------------------------------------------------------------------
// Attention: f16 flash, ex2.approx.f16x2, l via ones-column in V (d=18).
// 2 q-tiles per warp in the j-loop — K/V ldmatrix shared across both.
// ---------------------------------------------------------------------------
#define KPITCH 40
#define VPITCH 24
#define ATTN_SMEM_BYTES ((NSEG*KPITCH + NSEG*VPITCH) * 2)   // 131072

__global__ __launch_bounds__(512) void attn_kernel()
{
    int seg  = blockIdx.x;
    int b    = seg / (NHD * SFN);
    int rest = seg % (NHD * SFN);
    int hd   = rest / SFN;
    int sp   = rest % SFN;
    int base = b * NTOK + sp * NSEG;
    const int QKVROW = 3 * EE;

    extern __shared__ __half smh[];
    __half* Ks = smh;                       // [NSEG][KPITCH]
    __half* Vs = smh + NSEG * KPITCH;       // [NSEG][VPITCH]

    const uint32_t* qk32 = reinterpret_cast<const uint32_t*>(g_qkv_h);
    uint32_t* Ks32 = reinterpret_cast<uint32_t*>(Ks);
    uint32_t* Vs32 = reinterpret_cast<uint32_t*>(Vs);

    for (int idx = threadIdx.x; idx < NSEG * (KPITCH/2); idx += 512) {
        int i = idx / (KPITCH/2), d2 = idx - i * (KPITCH/2);
        uint32_t v = 0u;
        if (d2 < 9)
            v = qk32[(((size_t)(base + i) * QKVROW + EE + hd * DHH) >> 1) + d2];
        Ks32[i * (KPITCH/2) + d2] = v;
    }
    for (int idx = threadIdx.x; idx < NSEG * (VPITCH/2); idx += 512) {
        int i = idx / (VPITCH/2), d2 = idx - i * (VPITCH/2);
        uint32_t v = 0u;
        if (d2 < 9)
            v = qk32[(((size_t)(base + i) * QKVROW + 2*EE + hd * DHH) >> 1) + d2];
        else if (d2 == 9)
            v = 0x00003C00u;                 // {1.0h, 0} -> l-ones at d=18
        Vs32[i * (VPITCH/2) + d2] = v;
    }
    __syncthreads();

    int lane = threadIdx.x & 31, warp = threadIdx.x >> 5;
    int g = lane >> 2, t = lane & 3;
    int lr = lane & 7, lq = (lane >> 3) & 3;

    uint32_t ksb = (uint32_t)__cvta_generic_to_shared(Ks);
    uint32_t vsb = (uint32_t)__cvta_generic_to_shared(Vs);
    uint32_t kaddr_base = ksb + (((lr + (lq>>1)*8) * KPITCH + (lq&1)*8) << 1);
    uint32_t vaddr_base = vsb + (((lane & 15) * VPITCH) << 1);

    uint32_t* o32 = reinterpret_cast<uint32_t*>(g_o_h);

    #pragma unroll
    for (int qp = 0; qp < 2; qp++) {
        int q0A = (warp + qp*32) * 16;
        int q0B = q0A + 256;

        const uint32_t* qAa = qk32 + (((size_t)(base + q0A + g)     * QKVROW + hd * DHH) >> 1);
        const uint32_t* qAb = qk32 + (((size_t)(base + q0A + g + 8) * QKVROW + hd * DHH) >> 1);
        const uint32_t* qBa = qk32 + (((size_t)(base + q0B + g)     * QKVROW + hd * DHH) >> 1);
        const uint32_t* qBb = qk32 + (((size_t)(base + q0B + g + 8) * QKVROW + hd * DHH) >> 1);

        uint32_t qa[2][4], qb[2][4];
        qa[0][0] = qAa[t];   qa[0][1] = qAb[t];
        qa[0][2] = qAa[t+4]; qa[0][3] = qAb[t+4];
        qa[1][0] = (t == 0) ? qAa[8] : 0u;
        qa[1][1] = (t == 0) ? qAb[8] : 0u;
        qa[1][2] = 0u; qa[1][3] = 0u;
        qb[0][0] = qBa[t];   qb[0][1] = qBb[t];
        qb[0][2] = qBa[t+4]; qb[0][3] = qBb[t+4];
        qb[1][0] = (t == 0) ? qBa[8] : 0u;
        qb[1][1] = (t == 0) ? qBb[8] : 0u;
        qb[1][2] = 0u; qb[1][3] = 0u;

        float oA[3][4], oB[3][4];
        #pragma unroll
        for (int dn = 0; dn < 3; dn++)
            #pragma unroll
            for (int i = 0; i < 4; i++) { oA[dn][i] = 0.f; oB[dn][i] = 0.f; }

        uint32_t kaddr = kaddr_base;
        uint32_t vaddr = vaddr_base;
        for (int j0 = 0; j0 < NSEG; j0 += 16) {
            uint32_t kf0[4], kf1[4];
            ldsm_x4(kf0, kaddr);
            ldsm_x4(kf1, kaddr + 32);

            float sA0[4] = {0.f,0.f,0.f,0.f}, sA1[4] = {0.f,0.f,0.f,0.f};
            float sB0[4] = {0.f,0.f,0.f,0.f}, sB1[4] = {0.f,0.f,0.f,0.f};
            mma_f16(sA0, qa[0], kf0[0], kf0[1]);
            mma_f16(sA1, qa[0], kf0[2], kf0[3]);
            mma_f16(sA0, qa[1], kf1[0], kf1[1]);
            mma_f16(sA1, qa[1], kf1[2], kf1[3]);
            mma_f16(sB0, qb[0], kf0[0], kf0[1]);
            mma_f16(sB1, qb[0], kf0[2], kf0[3]);
            mma_f16(sB0, qb[1], kf1[0], kf1[1]);
            mma_f16(sB1, qb[1], kf1[2], kf1[3]);

            uint32_t paA[4], paB[4];
            paA[0] = ex2h2(cvth2(sA0[0], sA0[1]));
            paA[1] = ex2h2(cvth2(sA0[2], sA0[3]));
            paA[2] = ex2h2(cvth2(sA1[0], sA1[1]));
            paA[3] = ex2h2(cvth2(sA1[2], sA1[3]));
            paB[0] = ex2h2(cvth2(sB0[0], sB0[1]));
            paB[1] = ex2h2(cvth2(sB0[2], sB0[3]));
            paB[2] = ex2h2(cvth2(sB1[0], sB1[1]));
            paB[3] = ex2h2(cvth2(sB1[2], sB1[3]));

            uint32_t vf[2];
            ldsm_x2t(vf, vaddr);
            mma_f16(oA[0], paA, vf[0], vf[1]);
            mma_f16(oB[0], paB, vf[0], vf[1]);
            ldsm_x2t(vf, vaddr + 16);
            mma_f16(oA[1], paA, vf[0], vf[1]);
            mma_f16(oB[1], paB, vf[0], vf[1]);
            ldsm_x2t(vf, vaddr + 32);
            mma_f16(oA[2], paA, vf[0], vf[1]);
            mma_f16(oB[2], paB, vf[0], vf[1]);

            kaddr += 16 * KPITCH * 2;
            vaddr += 16 * VPITCH * 2;
        }

        int srcl = (lane & 28) | 1;
        float lgA  = __shfl_sync(0xffffffffu, oA[2][0], srcl);
        float lgA8 = __shfl_sync(0xffffffffu, oA[2][2], srcl);
        float lgB  = __shfl_sync(0xffffffffu, oB[2][0], srcl);
        float lgB8 = __shfl_sync(0xffffffffu, oB[2][2], srcl);
        float igA = 1.f / lgA, igA8 = 1.f / lgA8;
        float igB = 1.f / lgB, igB8 = 1.f / lgB8;

        #pragma unroll
        for (int dn = 0; dn < 3; dn++) {
            int dc = dn * 8 + 2 * t;
            if (dc < DHH) {
                o32[((size_t)(base + q0A + g)     * EE + hd*DHH + dc) >> 1] = packh2(oA[dn][0]*igA,  oA[dn][1]*igA);
                o32[((size_t)(base + q0A + g + 8) * EE + hd*DHH + dc) >> 1] = packh2(oA[dn][2]*igA8, oA[dn][3]*igA8);
                o32[((size_t)(base + q0B + g)     * EE + hd*DHH + dc) >> 1] = packh2(oB[dn][0]*igB,  oB[dn][1]*igB);
                o32[((size_t)(base + q0B + g + 8) * EE + hd*DHH + dc) >> 1] = packh2(oB[dn][2]*igB8, oB[dn][3]*igB8);
            }
        }
    }
}

// ---------------------------------------------------------------------------
// Fold: t_next = m(h)·m(w)·t + gather(branch).  (fold∘unfold = diag(m))
// ---------------------------------------------------------------------------
__global__ void fold_kernel(const float* __restrict__ img)
{
    int idx = blockIdx.x * blockDim.x + threadIdx.x;
    if (idx >= BB*CC*HH*WW) return;
    int w = idx & 63;
    int h = (idx >> 6) & 63;
    int c = (idx >> 12) & 31;
    int b =  idx >> 17;

    float mh = (h == 0 || h == HH-1) ? 2.f : 3.f;
    float mw = (w == 0 || w == WW-1) ? 2.f : 3.f;
    float sum = img[idx] * (mh * mw);

    #pragma unroll
    for (int i = 0; i < 3; i++) {
        int hh = h + 1 - i;
        if (hh < 0 || hh >= HH) continue;
        #pragma unroll
        for (int j = 0; j < 3; j++) {
            int ww = w + 1 - j;
            if (ww < 0 || ww >= WW) continue;
            sum += g_br[(size_t)(c*9 + i*3 + j)*MTOT + b*NTOK + hh*WW + ww];
        }
    }
    g_t[idx] = sum;
}

// ---------------------------------------------------------------------------
// Final: out = x + elu(conv3x3(t) + conv_b)
// ---------------------------------------------------------------------------
__global__ void conv_elu_kernel(const float* __restrict__ x,
                                const float* __restrict__ cw,
                                const float* __restrict__ cb,
                                float* __restrict__ out)
{
    int idx = blockIdx.x * blockDim.x + threadIdx.x;
    if (idx >= BB*CC*HH*WW) return;
    int w  = idx & 63;
    int h  = (idx >> 6) & 63;
    int co = (idx >> 12) & 31;
    int b  =  idx >> 17;

    float sum = cb[co];
    for (int ci = 0; ci < CC; ci++) {
        const float* tplane = &g_t[((size_t)(b*CC + ci))*HH*WW];
        const float* wk = &cw[((size_t)(co*CC + ci))*9];
        #pragma unroll
        for (int kh = 0; kh < 3; kh++) {
            int hh = h + kh - 1;
            if (hh < 0 || hh >= HH) continue;
            #pragma unroll
            for (int kw = 0; kw < 3; kw++) {
                int ww = w + kw - 1;
                if (ww < 0 || ww >= WW) continue;
                sum = fmaf(tplane[hh*WW + ww], wk[kh*3 + kw], sum);
            }
        }
    }
    float e = sum > 0.f ? sum : expm1f(sum);
    out[idx] = x[idx] + e;
}

// ---------------------------------------------------------------------------
// Launch
// ---------------------------------------------------------------------------
extern "C" void kernel_launch(void* const* d_in, const int* in_sizes, int n_in,
                              void* d_out, int out_size)
{
    (void)in_sizes; (void)n_in; (void)out_size;
    const float* x     = (const float*)d_in[0];
    const float* ln_g  = (const float*)d_in[1];
    const float* ln_b  = (const float*)d_in[2];
    const float* convw = (const float*)d_in[3];
    const float* convb = (const float*)d_in[4];
    float* out = (float*)d_out;

    float *p_t, *p_br;
    __half *p_colsn, *p_xr, *p_qkv, *p_o, *p_w;
    cudaGetSymbolAddress((void**)&p_t,     g_t);
    cudaGetSymbolAddress((void**)&p_br,    g_br);
    cudaGetSymbolAddress((void**)&p_colsn, g_colsn_h);
    cudaGetSymbolAddress((void**)&p_xr,    g_xr_h);
    cudaGetSymbolAddress((void**)&p_qkv,   g_qkv_h);
    cudaGetSymbolAddress((void**)&p_o,     g_o_h);
    cudaGetSymbolAddress((void**)&p_w,     g_w_h);

    cudaFuncSetAttribute(attn_kernel, cudaFuncAttributeMaxDynamicSharedMemorySize, ATTN_SMEM_BYTES);

    const int NPIX = BB*CC*HH*WW;

    offt_kernel<<<1, 288>>>();

    WPtrs wp;
    for (int L = 0; L < 3; L++) {
        wp.wr[L]   = (const float*)d_in[5 + 5*L + 0];
        wp.wqkv[L] = (const float*)d_in[5 + 5*L + 2];
        wp.we[L]   = (const float*)d_in[5 + 5*L + 3];
    }
    wconv_kernel<<<(3*WL_STRIDE + 255)/256, 256>>>(wp, p_w);

    for (int L = 0; L < 3; L++) {
        const float* br = (const float*)d_in[5 + 5*L + 1];
        const float* be = (const float*)d_in[5 + 5*L + 4];
        const __half* wr   = p_w + (size_t)L * WL_STRIDE;
        const __half* wqkv = wr + WQKV_OFF;
        const __half* we   = wr + WE_OFF;
        const float* img = (L == 0) ? x : p_t;

        unfold_ln_kernel<<<MTOT/8, 256>>>(img, ln_g, ln_b);
        // xr = colsn @ wr^T + br   (f16 out, tok-major)
        gemm_h_kernel<288, true><<<dim3(EE/48, MTOT/128), 256>>>(
            p_colsn, wr, br, p_xr, EE);
        // qkv = xr @ wqkv^T        (f16 out, Q pre-scaled)
        gemm_h_kernel<144, true><<<dim3(3*EE/48, MTOT/128), 256>>>(
            p_xr, wqkv, nullptr, p_qkv, 3*EE);
        attn_kernel<<<BB*NHD*SFN, 512, ATTN_SMEM_BYTES>>>();
        // branch = o @ we^T + be   (fp32 d-major out)
        gemm_h_kernel<144, false><<<dim3(DD/48, MTOT/128), 256>>>(
            p_o, we, be, p_br, DD);
        // t = m·t + fold(branch)
        fold_kernel<<<(NPIX + 255)/256, 256>>>(img);
    }
    conv_elu_kernel<<<(NPIX + 255)/256, 256>>>(x, convw, convb, out);
}

// round 11
// speedup vs baseline: 1.1439x; 1.0598x over previous
#include <cuda_runtime.h>
#include <cuda_fp16.h>
#include <math.h>
#include <stdint.h>

// Problem constants
#define BB   4
#define CC   32
#define HH   64
#define WW   64
#define DD   288          // C*K*K
#define EE   144          // D/2
#define NHD  8            // heads
#define DHH  18           // head dim
#define SFN  4            // split factor
#define NTOK 4096         // H*W tokens per batch
#define NSEG 1024         // NTOK / SF
#define MTOT (BB*NTOK)    // 16384 tokens total

// weight buffer layout (f16), per layer
#define WR_ELEMS   (EE*DD)
#define WQKV_ELEMS (3*EE*EE)
#define WE_ELEMS   (DD*EE)
#define WL_STRIDE  (WR_ELEMS + WQKV_ELEMS + WE_ELEMS)
#define WQKV_OFF   WR_ELEMS
#define WE_OFF     (WR_ELEMS + WQKV_ELEMS)

// ---- f16 mma / ldmatrix / cp.async helpers ---------------------------------
__device__ __forceinline__ void mma_f16(float* c, const uint32_t* a, uint32_t b0, uint32_t b1) {
    asm("mma.sync.aligned.m16n8k16.row.col.f32.f16.f16.f32 "
        "{%0,%1,%2,%3},{%4,%5,%6,%7},{%8,%9},{%0,%1,%2,%3};"
        : "+f"(c[0]), "+f"(c[1]), "+f"(c[2]), "+f"(c[3])
        : "r"(a[0]), "r"(a[1]), "r"(a[2]), "r"(a[3]), "r"(b0), "r"(b1));
}
__device__ __forceinline__ void ldsm_x4(uint32_t* r, uint32_t addr) {
    asm volatile("ldmatrix.sync.aligned.m8n8.x4.shared.b16 {%0,%1,%2,%3},[%4];"
        : "=r"(r[0]), "=r"(r[1]), "=r"(r[2]), "=r"(r[3]) : "r"(addr));
}
__device__ __forceinline__ void ldsm_x2(uint32_t* r, uint32_t addr) {
    asm volatile("ldmatrix.sync.aligned.m8n8.x2.shared.b16 {%0,%1},[%2];"
        : "=r"(r[0]), "=r"(r[1]) : "r"(addr));
}
__device__ __forceinline__ void ldsm_x2t(uint32_t* r, uint32_t addr) {
    asm volatile("ldmatrix.sync.aligned.m8n8.x2.trans.shared.b16 {%0,%1},[%2];"
        : "=r"(r[0]), "=r"(r[1]) : "r"(addr));
}
__device__ __forceinline__ uint32_t cvth2(float lo, float hi) {
    uint32_t r; asm("cvt.rn.f16x2.f32 %0,%1,%2;" : "=r"(r) : "f"(hi), "f"(lo)); return r;
}
__device__ __forceinline__ uint32_t ex2h2(uint32_t x) {
    uint32_t r; asm("ex2.approx.f16x2 %0,%1;" : "=r"(r) : "r"(x)); return r;
}
__device__ __forceinline__ uint32_t packh2(float lo, float hi) {
    __half2 h = __floats2half2_rn(lo, hi);
    return *reinterpret_cast<uint32_t*>(&h);
}
__device__ __forceinline__ void cp16(uint32_t saddr, const void* g) {
    asm volatile("cp.async.ca.shared.global [%0], [%1], 16;" :: "r"(saddr), "l"(g));
}
__device__ __forceinline__ void cp_commit() {
    asm volatile("cp.async.commit_group;");
}
__device__ __forceinline__ void cp_wait0() {
    asm volatile("cp.async.wait_group 0;");
}

// Scratch (device globals: allocation-free rule)
__device__ float  g_t[BB*CC*HH*WW];        // current image (fp32)
__device__ float  g_br[DD*MTOT];           // EMHA branch out, fp32 D-MAJOR [d][tok]
__device__ __half g_colsn_h[MTOT*DD];      // layernormed cols (f16, tok-major)
__device__ __half g_xr_h[MTOT*EE];         // reduced tokens (f16)
__device__ __half g_qkv_h[MTOT*3*EE];      // qkv (f16, Q pre-scaled)
__device__ __half g_o_h[MTOT*EE];          // attention output (f16)
__device__ __half g_w_h[3*WL_STRIDE];      // converted weights, 3 layers
__device__ int    g_offt[DD];              // packed unfold offsets

// ---------------------------------------------------------------------------
// One-time: packed unfold offsets.
// ---------------------------------------------------------------------------
__global__ void offt_kernel()
{
    int d = threadIdx.x;
    if (d >= DD) return;
    int c = d / 9, r = d - 9*c;
    int kh = r / 3, kw = r - 3*kh;
    int off = c*4096 + (kh-1)*64 + (kw-1);
    g_offt[d] = (off + 65) | (kh << 20) | (kw << 22);
}

// ---------------------------------------------------------------------------
// Weight conversion fp32 -> f16, all 3 layers in ONE launch.
// ---------------------------------------------------------------------------
struct WPtrs {
    const float* wr[3];
    const float* wqkv[3];
    const float* we[3];
};
__global__ void wconv_kernel(WPtrs p, __half* __restrict__ dst)
{
    const float qs = 0.235702260395515841f * 1.4426950408889634f;
    int i = blockIdx.x * 256 + threadIdx.x;
    if (i >= 3 * WL_STRIDE) return;
    int L = i / WL_STRIDE;
    int j = i - L * WL_STRIDE;
    float v;
    if (j < WR_ELEMS) v = p.wr[L][j];
    else if (j < WE_OFF) {
        int k = j - WQKV_OFF;
        v = p.wqkv[L][k];
        if (k < EE * EE) v *= qs;
    } else v = p.we[L][j - WE_OFF];
    dst[i] = __float2half(v);
}

// ---------------------------------------------------------------------------
// Fused unfold + LayerNorm. One WARP per token; table-driven offsets.
// ---------------------------------------------------------------------------
__global__ __launch_bounds__(256) void unfold_ln_kernel(
    const float* __restrict__ img,
    const float* __restrict__ lng,
    const float* __restrict__ lnb)
{
    __shared__ int soff[DD];
    for (int i = threadIdx.x; i < DD; i += 256) soff[i] = g_offt[i];
    __syncthreads();

    int warp = threadIdx.x >> 5, lane = threadIdx.x & 31;
    int tok = blockIdx.x * 8 + warp;
    int b = tok >> 12;
    int n = tok & (NTOK - 1);
    int h = n >> 6, w = n & 63;
    int base = b*CC*4096 + h*64 + w;

    float v[9];
    float s = 0.f, q = 0.f;
    if (h >= 1 && h <= 62 && w >= 1 && w <= 62) {
        #pragma unroll
        for (int i = 0; i < 9; i++) {
            int pk = soff[i*32 + lane];
            float x = img[base + (pk & 0xFFFFF) - 65];
            v[i] = x; s += x; q = fmaf(x, x, q);
        }
    } else {
        #pragma unroll
        for (int i = 0; i < 9; i++) {
            int pk = soff[i*32 + lane];
            int kh = (pk >> 20) & 3, kw = (pk >> 22) & 3;
            int hh = h + kh - 1, ww = w + kw - 1;
            float x = 0.f;
            if ((unsigned)hh < HH && (unsigned)ww < WW)
                x = img[base + (pk & 0xFFFFF) - 65];
            v[i] = x; s += x; q = fmaf(x, x, q);
        }
    }
    #pragma unroll
    for (int o = 16; o > 0; o >>= 1) {
        s += __shfl_xor_sync(0xffffffffu, s, o);
        q += __shfl_xor_sync(0xffffffffu, q, o);
    }
    float mu = s * (1.f / DD);
    float rstd = rsqrtf(q * (1.f / DD) - mu * mu + 1e-5f);
    #pragma unroll
    for (int i = 0; i < 9; i++) {
        int d = i * 32 + lane;
        g_colsn_h[(size_t)tok*DD + d] =
            __float2half((v[i] - mu) * rstd * __ldg(&lng[d]) + __ldg(&lnb[d]));
    }
}

// ---------------------------------------------------------------------------
// f16 GEMM with cp.async DOUBLE-BUFFERED staging + ldmatrix.
// C(M,N) = A(M,K)*W(N,K)^T (+bias). CTA tile 128x48, warp 32x24, k-chunk 48.
// Smem: 2 buffers x (128 A-rows + 48 B-rows) x APITCH.
// ---------------------------------------------------------------------------
#define APITCH 56
#define BUFHALF (176*APITCH)    // halves per buffer (A:0..127, B:128..175)

template<int K, bool BOUT>
__global__ __launch_bounds__(256) void gemm_h_kernel(
    const __half* __restrict__ A, const __half* __restrict__ W,
    const float* __restrict__ bias,
    void* __restrict__ Cout, int Ncol)
{
    __shared__ __half Sm[2*BUFHALF];

    int tid = threadIdx.x;
    int warp = tid >> 5, lane = tid & 31;
    int g = lane >> 2, t = lane & 3;
    int wm = warp & 3, wn = warp >> 2;
    int rowB = blockIdx.y * 128;
    int colB = blockIdx.x * 48;

    float acc[2][3][4];
    #pragma unroll
    for (int i = 0; i < 2; i++)
        #pragma unroll
        for (int j = 0; j < 3; j++)
            #pragma unroll
            for (int k = 0; k < 4; k++) acc[i][j][k] = 0.f;

    uint32_t smb = (uint32_t)__cvta_generic_to_shared(Sm);
    int lr = lane & 7, lq = (lane >> 3) & 3;
    uint32_t aoff0 = smb + (((wm*32 + lr + (lq&1)*8) * APITCH + (lq>>1)*8) << 1);
    uint32_t aoff1 = aoff0 + ((16*APITCH) << 1);
    uint32_t boff4 = smb + (((128 + wn*24 + lr + (lq>>1)*8) * APITCH + (lq&1)*8) << 1);
    uint32_t boff2 = smb + (((128 + wn*24 + 16 + lr) * APITCH + ((lane>>3)&1)*8) << 1);

    // staging lane roles (precomputed)
    int arow = tid / 6 * 0;    // placeholder to keep regs low; compute below
    // A: 768 16B-chunks, 3 per thread; B: 288 chunks, threads 0..287 roles
    int ar0 = tid / 6,  as0 = tid - ar0*6;
    int ar1 = (tid+256) / 6, as1 = (tid+256) - ar1*6;
    int ar2 = (tid+512) / 6, as2 = (tid+512) - ar2*6;
    (void)arow;

    auto stage = [&](int kc, int buf) {
        uint32_t sb = smb + ((buf * BUFHALF) << 1);
        cp16(sb + ((ar0*APITCH + as0*8) << 1), A + (size_t)(rowB + ar0)*K + kc + as0*8);
        cp16(sb + ((ar1*APITCH + as1*8) << 1), A + (size_t)(rowB + ar1)*K + kc + as1*8);
        cp16(sb + ((ar2*APITCH + as2*8) << 1), A + (size_t)(rowB + ar2)*K + kc + as2*8);
        if (tid < 288) {
            int row = tid / 6, seg = tid - row*6;
            cp16(sb + (((128 + row)*APITCH + seg*8) << 1),
                 W + (size_t)(colB + row)*K + kc + seg*8);
        } else {
            int i2 = tid - 256 + 256;   // 256..287 handled above? no: second pass
        }
        int idx = tid + 256;
        if (idx < 288) {
            int row = idx / 6, seg = idx - row*6;
            cp16(sb + (((128 + row)*APITCH + seg*8) << 1),
                 W + (size_t)(colB + row)*K + kc + seg*8);
        }
        cp_commit();
    };

    const int NCH = K / 48;
    stage(0, 0);

    for (int ch = 0; ch < NCH; ch++) {
        cp_wait0();
        __syncthreads();
        if (ch + 1 < NCH) stage((ch + 1) * 48, (ch + 1) & 1);

        uint32_t bofs = ((ch & 1) * BUFHALF) << 1;
        #pragma unroll
        for (int kk = 0; kk < 48; kk += 16) {
            uint32_t a0[4], a1[4], b01[4], b2[2];
            ldsm_x4(a0, aoff0 + bofs + (kk << 1));
            ldsm_x4(a1, aoff1 + bofs + (kk << 1));
            ldsm_x4(b01, boff4 + bofs + (kk << 1));
            ldsm_x2(b2, boff2 + bofs + (kk << 1));
            mma_f16(acc[0][0], a0, b01[0], b01[1]);
            mma_f16(acc[0][1], a0, b01[2], b01[3]);
            mma_f16(acc[0][2], a0, b2[0],  b2[1]);
            mma_f16(acc[1][0], a1, b01[0], b01[1]);
            mma_f16(acc[1][1], a1, b01[2], b01[3]);
            mma_f16(acc[1][2], a1, b2[0],  b2[1]);
        }
        __syncthreads();
    }

    #pragma unroll
    for (int mt = 0; mt < 2; mt++) {
        int r0 = rowB + wm*32 + mt*16 + g;
        int r1 = r0 + 8;
        #pragma unroll
        for (int nt = 0; nt < 3; nt++) {
            int cc = colB + wn*24 + nt*8 + 2*t;
            float v0 = acc[mt][nt][0], v1 = acc[mt][nt][1];
            float v2 = acc[mt][nt][2], v3 = acc[mt][nt][3];
            if (bias) {
                float b0 = bias[cc], b1 = bias[cc+1];
                v0 += b0; v1 += b1; v2 += b0; v3 += b1;
            }
            if (BOUT) {
                uint32_t* C = (uint32_t*)Cout;
                C[((size_t)r0 * Ncol + cc) >> 1] = packh2(v0, v1);
                C[((size_t)r1 * Ncol + cc) >> 1] = packh2(v2, v3);
            } else {
                float* C = (float*)Cout;
                size_t i00 = (size_t)cc*MTOT + r0, i10 = i00 + MTOT;
                size_t i01 = (size_t)cc*MTOT + r1, i11 = i01 + MTOT;
                C[i00] = v0; C[i10] = v1; C[i01] = v2; C[i11] = v3;
            }
        }
    }
}

// ---------------------------------------------------------------------------
// Attention (round-8 form): f16 flash, ex2.approx.f16x2, l via ones-column
// in V (d=18). One q-tile per warp iteration.
// ---------------------------------------------------------------------------
#define KPITCH 40
#define VPITCH 24
#define ATTN_SMEM_BYTES ((NSEG*KPITCH + NSEG*VPITCH) * 2)   // 131072

__global__ __launch_bounds__(512) void attn_kernel()
{
    int seg  = blockIdx.x;
    int b    = seg / (NHD * SFN);
    int rest = seg % (NHD * SFN);
    int hd   = rest / SFN;
    int sp   = rest % SFN;
    int base = b * NTOK + sp * NSEG;
    const int QKVROW = 3 * EE;

    extern __shared__ __half smh[];
    __half* Ks = smh;                       // [NSEG][KPITCH]
    __half* Vs = smh + NSEG * KPITCH;       // [NSEG][VPITCH]

    const uint32_t* qk32 = reinterpret_cast<const uint32_t*>(g_qkv_h);
    uint32_t* Ks32 = reinterpret_cast<uint32_t*>(Ks);
    uint32_t* Vs32 = reinterpret_cast<uint32_t*>(Vs);

    for (int idx = threadIdx.x; idx < NSEG * (KPITCH/2); idx += 512) {
        int i = idx / (KPITCH/2), d2 = idx - i * (KPITCH/2);
        uint32_t v = 0u;
        if (d2 < 9)
            v = qk32[(((size_t)(base + i) * QKVROW + EE + hd * DHH) >> 1) + d2];
        Ks32[i * (KPITCH/2) + d2] = v;
    }
    for (int idx = threadIdx.x; idx < NSEG * (VPITCH/2); idx += 512) {
        int i = idx / (VPITCH/2), d2 = idx - i * (VPITCH/2);
        uint32_t v = 0u;
        if (d2 < 9)
            v = qk32[(((size_t)(base + i) * QKVROW + 2*EE + hd * DHH) >> 1) + d2];
        else if (d2 == 9)
            v = 0x00003C00u;                 // {1.0h, 0} -> l-ones at d=18
        Vs32[i * (VPITCH/2) + d2] = v;
    }
    __syncthreads();

    int lane = threadIdx.x & 31, warp = threadIdx.x >> 5;
    int g = lane >> 2, t = lane & 3;
    int lr = lane & 7, lq = (lane >> 3) & 3;

    uint32_t ksb = (uint32_t)__cvta_generic_to_shared(Ks);
    uint32_t vsb = (uint32_t)__cvta_generic_to_shared(Vs);
    uint32_t kaddr_base = ksb + (((lr + (lq>>1)*8) * KPITCH + (lq&1)*8) << 1);
    uint32_t vaddr_base = vsb + (((lane & 15) * VPITCH) << 1);

    for (int qt = warp; qt < NSEG / 16; qt += 16) {
        int q0 = qt * 16;
        const uint32_t* q32a = qk32 + (((size_t)(base + q0 + g)     * QKVROW + hd * DHH) >> 1);
        const uint32_t* q32b = qk32 + (((size_t)(base + q0 + g + 8) * QKVROW + hd * DHH) >> 1);

        uint32_t qa[2][4];
        qa[0][0] = q32a[t];
        qa[0][1] = q32b[t];
        qa[0][2] = q32a[t + 4];
        qa[0][3] = q32b[t + 4];
        qa[1][0] = (t == 0) ? q32a[8] : 0u;
        qa[1][1] = (t == 0) ? q32b[8] : 0u;
        qa[1][2] = 0u; qa[1][3] = 0u;

        float o[3][4];
        #pragma unroll
        for (int dn = 0; dn < 3; dn++)
            #pragma unroll
            for (int i = 0; i < 4; i++) o[dn][i] = 0.f;

        uint32_t kaddr = kaddr_base;
        uint32_t vaddr = vaddr_base;
        for (int j0 = 0; j0 < NSEG; j0 += 16) {
            uint32_t kf0[4], kf1[4];
            ldsm_x4(kf0, kaddr);
            ldsm_x4(kf1, kaddr + 32);
            float s0[4] = {0.f,0.f,0.f,0.f};
            float s1[4] = {0.f,0.f,0.f,0.f};
            mma_f16(s0, qa[0], kf0[0], kf0[1]);
            mma_f16(s1, qa[0], kf0[2], kf0[3]);
            mma_f16(s0, qa[1], kf1[0], kf1[1]);
            mma_f16(s1, qa[1], kf1[2], kf1[3]);

            uint32_t pa[4];
            pa[0] = ex2h2(cvth2(s0[0], s0[1]));
            pa[1] = ex2h2(cvth2(s0[2], s0[3]));
            pa[2] = ex2h2(cvth2(s1[0], s1[1]));
            pa[3] = ex2h2(cvth2(s1[2], s1[3]));

            uint32_t vf[2];
            ldsm_x2t(vf, vaddr);
            mma_f16(o[0], pa, vf[0], vf[1]);
            ldsm_x2t(vf, vaddr + 16);
            mma_f16(o[1], pa, vf[0], vf[1]);
            ldsm_x2t(vf, vaddr + 32);
            mma_f16(o[2], pa, vf[0], vf[1]);

            kaddr += 16 * KPITCH * 2;
            vaddr += 16 * VPITCH * 2;
        }

        int srcl = (lane & 28) | 1;
        float lg  = __shfl_sync(0xffffffffu, o[2][0], srcl);
        float lg8 = __shfl_sync(0xffffffffu, o[2][2], srcl);
        float ig = 1.f / lg, ig8 = 1.f / lg8;

        uint32_t* o32 = reinterpret_cast<uint32_t*>(g_o_h);
        #pragma unroll
        for (int dn = 0; dn < 3; dn++) {
            int dc = dn * 8 + 2 * t;
            if (dc < DHH) {
                o32[((size_t)(base + q0 + g)     * EE + hd*DHH + dc) >> 1] = packh2(o[dn][0]*ig,  o[dn][1]*ig);
                o32[((size_t)(base + q0 + g + 8) * EE + hd*DHH + dc) >> 1] = packh2(o[dn][2]*ig8, o[dn][3]*ig8);
            }
        }
    }
}

// ---------------------------------------------------------------------------
// Fold: t_next = m(h)·m(w)·t + gather(branch).
// ---------------------------------------------------------------------------
__global__ void fold_kernel(const float* __restrict__ img)
{
    int idx = blockIdx.x * blockDim.x + threadIdx.x;
    if (idx >= BB*CC*HH*WW) return;
    int w = idx & 63;
    int h = (idx >> 6) & 63;
    int c = (idx >> 12) & 31;
    int b =  idx >> 17;

    float mh = (h == 0 || h == HH-1) ? 2.f : 3.f;
    float mw = (w == 0 || w == WW-1) ? 2.f : 3.f;
    float sum = img[idx] * (mh * mw);

    #pragma unroll
    for (int i = 0; i < 3; i++) {
        int hh = h + 1 - i;
        if (hh < 0 || hh >= HH) continue;
        #pragma unroll
        for (int j = 0; j < 3; j++) {
            int ww = w + 1 - j;
            if (ww < 0 || ww >= WW) continue;
            sum += g_br[(size_t)(c*9 + i*3 + j)*MTOT + b*NTOK + hh*WW + ww];
        }
    }
    g_t[idx] = sum;
}

// ---------------------------------------------------------------------------
// Final: out = x + elu(conv3x3(t) + conv_b)
// ---------------------------------------------------------------------------
__global__ void conv_elu_kernel(const float* __restrict__ x,
                                const float* __restrict__ cw,
                                const float* __restrict__ cb,
                                float* __restrict__ out)
{
    int idx = blockIdx.x * blockDim.x + threadIdx.x;
    if (idx >= BB*CC*HH*WW) return;
    int w  = idx & 63;
    int h  = (idx >> 6) & 63;
    int co = (idx >> 12) & 31;
    int b  =  idx >> 17;

    float sum = cb[co];
    for (int ci = 0; ci < CC; ci++) {
        const float* tplane = &g_t[((size_t)(b*CC + ci))*HH*WW];
        const float* wk = &cw[((size_t)(co*CC + ci))*9];
        #pragma unroll
        for (int kh = 0; kh < 3; kh++) {
            int hh = h + kh - 1;
            if (hh < 0 || hh >= HH) continue;
            #pragma unroll
            for (int kw = 0; kw < 3; kw++) {
                int ww = w + kw - 1;
                if (ww < 0 || ww >= WW) continue;
                sum = fmaf(tplane[hh*WW + ww], wk[kh*3 + kw], sum);
            }
        }
    }
    float e = sum > 0.f ? sum : expm1f(sum);
    out[idx] = x[idx] + e;
}

// ---------------------------------------------------------------------------
// Launch
// ---------------------------------------------------------------------------
extern "C" void kernel_launch(void* const* d_in, const int* in_sizes, int n_in,
                              void* d_out, int out_size)
{
    (void)in_sizes; (void)n_in; (void)out_size;
    const float* x     = (const float*)d_in[0];
    const float* ln_g  = (const float*)d_in[1];
    const float* ln_b  = (const float*)d_in[2];
    const float* convw = (const float*)d_in[3];
    const float* convb = (const float*)d_in[4];
    float* out = (float*)d_out;

    float *p_t, *p_br;
    __half *p_colsn, *p_xr, *p_qkv, *p_o, *p_w;
    cudaGetSymbolAddress((void**)&p_t,     g_t);
    cudaGetSymbolAddress((void**)&p_br,    g_br);
    cudaGetSymbolAddress((void**)&p_colsn, g_colsn_h);
    cudaGetSymbolAddress((void**)&p_xr,    g_xr_h);
    cudaGetSymbolAddress((void**)&p_qkv,   g_qkv_h);
    cudaGetSymbolAddress((void**)&p_o,     g_o_h);
    cudaGetSymbolAddress((void**)&p_w,     g_w_h);

    cudaFuncSetAttribute(attn_kernel, cudaFuncAttributeMaxDynamicSharedMemorySize, ATTN_SMEM_BYTES);

    const int NPIX = BB*CC*HH*WW;

    offt_kernel<<<1, 288>>>();

    WPtrs wp;
    for (int L = 0; L < 3; L++) {
        wp.wr[L]   = (const float*)d_in[5 + 5*L + 0];
        wp.wqkv[L] = (const float*)d_in[5 + 5*L + 2];
        wp.we[L]   = (const float*)d_in[5 + 5*L + 3];
    }
    wconv_kernel<<<(3*WL_STRIDE + 255)/256, 256>>>(wp, p_w);

    for (int L = 0; L < 3; L++) {
        const float* br = (const float*)d_in[5 + 5*L + 1];
        const float* be = (const float*)d_in[5 + 5*L + 4];
        const __half* wr   = p_w + (size_t)L * WL_STRIDE;
        const __half* wqkv = wr + WQKV_OFF;
        const __half* we   = wr + WE_OFF;
        const float* img = (L == 0) ? x : p_t;

        unfold_ln_kernel<<<MTOT/8, 256>>>(img, ln_g, ln_b);
        gemm_h_kernel<288, true><<<dim3(EE/48, MTOT/128), 256>>>(
            p_colsn, wr, br, p_xr, EE);
        gemm_h_kernel<144, true><<<dim3(3*EE/48, MTOT/128), 256>>>(
            p_xr, wqkv, nullptr, p_qkv, 3*EE);
        attn_kernel<<<BB*NHD*SFN, 512, ATTN_SMEM_BYTES>>>();
        gemm_h_kernel<144, false><<<dim3(DD/48, MTOT/128), 256>>>(
            p_o, we, be, p_br, DD);
        fold_kernel<<<(NPIX + 255)/256, 256>>>(img);
    }
    conv_elu_kernel<<<(NPIX + 255)/256, 256>>>(x, convw, convb, out);
}